// round 3
// baseline (speedup 1.0000x reference)
#include <cuda_runtime.h>
#include <cstdint>
#include <math.h>

#define C_CLASSES 1024
#define ALLNUM    8192
#define DIMK      512
#define TOPK      410
#define BATCH     2048
#define LAMB      0.3f

// ---------------- scratch (static device globals: no allocation) ----------------
__device__ float g_invnorm[ALLNUM];                       // 32 KB
__device__ float g_G[DIMK * C_CLASSES];                   // 2 MB  G[d][c] = sum of class-c centers
__device__ float g_sim[(size_t)BATCH * ALLNUM];           // 64 MB similarity
__device__ float g_CL[(size_t)ALLNUM * C_CLASSES];        // 32 MB centers_logits
__device__ float g_lossb[BATCH];
__device__ float g_regb[ALLNUM];
__device__ int   g_is64;

// ---------------- helpers ----------------
__device__ __forceinline__ unsigned long long pk2(float x, float y) {
    unsigned long long r;
    asm("mov.b64 %0, {%1, %2};" : "=l"(r) : "f"(x), "f"(y));
    return r;
}
__device__ __forceinline__ unsigned long long ffma2(unsigned long long a,
                                                    unsigned long long b,
                                                    unsigned long long c) {
    unsigned long long d;
    asm("fma.rn.f32x2 %0, %1, %2, %3;" : "=l"(d) : "l"(a), "l"(b), "l"(c));
    return d;
}
__device__ __forceinline__ float2 upk2(unsigned long long v) {
    float lo, hi;
    asm("mov.b64 {%0, %1}, %2;" : "=f"(lo), "=f"(hi) : "l"(v));
    return make_float2(lo, hi);
}
__device__ __forceinline__ long long load_idx(const void* p, int i) {
    if (g_is64) return ((const long long*)p)[i];
    return (long long)((const int*)p)[i];
}

// ---------------- 0: int64 vs int32 index dtype detection ----------------
// target values are in [0,1024). If stored as int64 (little-endian), every odd
// 32-bit word is 0. If int32, odd words are random values in [0,1024):
// P(all 8 zero) = 1024^-8 ~ 0.
__global__ void k_detect(const unsigned int* __restrict__ t) {
    if (threadIdx.x == 0) {
        int is64 = 1;
        for (int k = 0; k < 8; k++)
            if (t[2 * k + 1] != 0u) is64 = 0;
        g_is64 = is64;
    }
}

// ---------------- 1: column inverse norms ----------------
__global__ void k_norm(const float* __restrict__ P) {
    int a = blockIdx.x * blockDim.x + threadIdx.x;   // 8192 threads, coalesced over a
    float s = 0.f;
    for (int d = 0; d < DIMK; d++) {
        float v = P[(size_t)d * ALLNUM + a];
        s = fmaf(v, v, s);
    }
    g_invnorm[a] = 1.0f / fmaxf(sqrtf(s), 1e-12f);
}

// ---------------- 2: class-summed centers G[d][c] ----------------
__global__ void k_groupsum(const float* __restrict__ P, const void* __restrict__ il) {
    __shared__ float g[C_CLASSES];
    int d = blockIdx.x;                               // 512 blocks
    for (int c = threadIdx.x; c < C_CLASSES; c += blockDim.x) g[c] = 0.f;
    __syncthreads();
    const float* Pd = P + (size_t)d * ALLNUM;
    for (int a = threadIdx.x; a < ALLNUM; a += blockDim.x)
        atomicAdd(&g[(int)load_idx(il, a)], Pd[a] * g_invnorm[a]);
    __syncthreads();
    for (int c = threadIdx.x; c < C_CLASSES; c += blockDim.x)
        g_G[d * C_CLASSES + c] = g[c];
}

// ---------------- 3: GEMM1  sim[b][a] = input[b,:] . (P[:,a]*invnorm[a]) ----------------
// M=2048, N=8192, K=512.  128x128 tile, 256 threads, 8x8/thread via packed f32x2 FMA.
__global__ __launch_bounds__(256, 2) void k_gemm_sim(const float* __restrict__ A,
                                                     const float* __restrict__ B) {
    __shared__ unsigned long long As2[16][129];        // A value duplicated-packed
    __shared__ __align__(16) float Bs[16][128];
    __shared__ float scs[128];
    const int N = ALLNUM, K = DIMK;
    int tid = threadIdx.x;
    int bm = blockIdx.y * 128, bn = blockIdx.x * 128;
    int tx = tid & 15, ty = tid >> 4;

    if (tid < 128) scs[tid] = g_invnorm[bn + tid];
    unsigned long long acc[8][4];
#pragma unroll
    for (int i = 0; i < 8; i++)
#pragma unroll
        for (int j = 0; j < 4; j++) acc[i][j] = 0ull;
    __syncthreads();

    for (int k0 = 0; k0 < K; k0 += 16) {
#pragma unroll
        for (int io = 0; io < 2; io++) {
            int flat = (tid + io * 256) * 4;
            int ar = flat >> 4, ac = flat & 15;
            float4 av = *(const float4*)(A + (size_t)(bm + ar) * K + k0 + ac);
            As2[ac + 0][ar] = pk2(av.x, av.x);
            As2[ac + 1][ar] = pk2(av.y, av.y);
            As2[ac + 2][ar] = pk2(av.z, av.z);
            As2[ac + 3][ar] = pk2(av.w, av.w);
            int br = flat >> 7, bc = flat & 127;
            float4 bv = *(const float4*)(B + (size_t)(k0 + br) * N + bn + bc);
            bv.x *= scs[bc]; bv.y *= scs[bc + 1]; bv.z *= scs[bc + 2]; bv.w *= scs[bc + 3];
            *(float4*)&Bs[br][bc] = bv;
        }
        __syncthreads();
#pragma unroll
        for (int kk = 0; kk < 16; kk++) {
            unsigned long long a2[8], b2[4];
            const unsigned long long* brow = (const unsigned long long*)&Bs[kk][0];
#pragma unroll
            for (int j = 0; j < 4; j++) b2[j] = brow[tx * 4 + j];
#pragma unroll
            for (int i = 0; i < 8; i++) a2[i] = As2[kk][ty * 8 + i];
#pragma unroll
            for (int i = 0; i < 8; i++)
#pragma unroll
                for (int j = 0; j < 4; j++) acc[i][j] = ffma2(a2[i], b2[j], acc[i][j]);
        }
        __syncthreads();
    }
#pragma unroll
    for (int i = 0; i < 8; i++) {
        float2 p0 = upk2(acc[i][0]), p1 = upk2(acc[i][1]);
        float2 p2 = upk2(acc[i][2]), p3 = upk2(acc[i][3]);
        size_t off = (size_t)(bm + ty * 8 + i) * N + bn + tx * 8;
        *(float4*)(g_sim + off)     = make_float4(p0.x, p0.y, p1.x, p1.y);
        *(float4*)(g_sim + off + 4) = make_float4(p2.x, p2.y, p3.x, p3.y);
    }
}

// ---------------- 4: GEMM2  CL[a][c] = invnorm[a] * (P[:,a] . G[:,c]) ----------------
// M=8192, N=1024, K=512. A read transposed from P (contiguous in a).
__global__ __launch_bounds__(256, 2) void k_gemm_reg(const float* __restrict__ P) {
    __shared__ unsigned long long As2[16][129];
    __shared__ __align__(16) float Bs[16][128];
    const int N = C_CLASSES, K = DIMK;
    int tid = threadIdx.x;
    int bm = blockIdx.y * 128, bn = blockIdx.x * 128;
    int tx = tid & 15, ty = tid >> 4;

    unsigned long long acc[8][4];
#pragma unroll
    for (int i = 0; i < 8; i++)
#pragma unroll
        for (int j = 0; j < 4; j++) acc[i][j] = 0ull;

    for (int k0 = 0; k0 < K; k0 += 16) {
#pragma unroll
        for (int io = 0; io < 2; io++) {
            int flat = (tid + io * 256) * 4;
            int r = flat >> 7, c = flat & 127;
            float4 pv = *(const float4*)(P + (size_t)(k0 + r) * ALLNUM + bm + c);
            As2[r][c + 0] = pk2(pv.x, pv.x);
            As2[r][c + 1] = pk2(pv.y, pv.y);
            As2[r][c + 2] = pk2(pv.z, pv.z);
            As2[r][c + 3] = pk2(pv.w, pv.w);
            float4 bv = *(const float4*)(g_G + (size_t)(k0 + r) * N + bn + c);
            *(float4*)&Bs[r][c] = bv;
        }
        __syncthreads();
#pragma unroll
        for (int kk = 0; kk < 16; kk++) {
            unsigned long long a2[8], b2[4];
            const unsigned long long* brow = (const unsigned long long*)&Bs[kk][0];
#pragma unroll
            for (int j = 0; j < 4; j++) b2[j] = brow[tx * 4 + j];
#pragma unroll
            for (int i = 0; i < 8; i++) a2[i] = As2[kk][ty * 8 + i];
#pragma unroll
            for (int i = 0; i < 8; i++)
#pragma unroll
                for (int j = 0; j < 4; j++) acc[i][j] = ffma2(a2[i], b2[j], acc[i][j]);
        }
        __syncthreads();
    }
#pragma unroll
    for (int i = 0; i < 8; i++) {
        float sc = g_invnorm[bm + ty * 8 + i];
        float2 p0 = upk2(acc[i][0]), p1 = upk2(acc[i][1]);
        float2 p2 = upk2(acc[i][2]), p3 = upk2(acc[i][3]);
        size_t off = (size_t)(bm + ty * 8 + i) * N + bn + tx * 8;
        *(float4*)(g_CL + off)     = make_float4(p0.x * sc, p0.y * sc, p1.x * sc, p1.y * sc);
        *(float4*)(g_CL + off + 4) = make_float4(p2.x * sc, p2.y * sc, p3.x * sc, p3.y * sc);
    }
}

// ---------------- 5: per-row top-k threshold + masked-softmax classify loss ----------------
// One CTA per batch row. 4-pass (8-bit digit) radix select on ordered float bits
// over the boosted similarities, then class-grouped masked sums.
__global__ __launch_bounds__(256) void k_classify(const void* __restrict__ target,
                                                  const void* __restrict__ il) {
    __shared__ unsigned int uvals[ALLNUM];   // 32 KB
    __shared__ unsigned int hist[256];
    __shared__ float slog[C_CLASSES];        // 4 KB
    __shared__ float red[256];
    __shared__ unsigned int sh_prefix;
    __shared__ int sh_k;

    int tid = threadIdx.x;
    int b = blockIdx.x;
    long long tgt = load_idx(target, b);
    const float* Srow = g_sim + (size_t)b * ALLNUM;

    for (int i = tid; i < ALLNUM; i += 256) {
        float v = Srow[i] + ((load_idx(il, i) == tgt) ? 1000.0f : 0.0f);
        unsigned int bits = __float_as_uint(v);
        uvals[i] = (bits & 0x80000000u) ? ~bits : (bits | 0x80000000u);
    }
    for (int c = tid; c < C_CLASSES; c += 256) slog[c] = 0.f;
    if (tid == 0) { sh_prefix = 0u; sh_k = TOPK; }
    __syncthreads();

    for (int shift = 24; shift >= 0; shift -= 8) {
        hist[tid] = 0u;
        __syncthreads();
        unsigned int pfx = sh_prefix;
        int k = sh_k;
        unsigned int hm = (shift == 24) ? 0u : (0xFFFFFFFFu << (shift + 8));
        for (int i = tid; i < ALLNUM; i += 256) {
            unsigned int u = uvals[i];
            if ((u & hm) == pfx) atomicAdd(&hist[(u >> shift) & 255u], 1u);
        }
        __syncthreads();
        if (tid == 0) {
            int cum = 0, d = 255;
            for (; d >= 0; d--) { cum += (int)hist[d]; if (cum >= k) break; }
            sh_k = k - (cum - (int)hist[d]);
            sh_prefix = pfx | ((unsigned int)d << shift);
        }
        __syncthreads();
    }
    unsigned int tau = sh_prefix;   // exact bit pattern of the TOPK-th largest boosted value

    for (int i = tid; i < ALLNUM; i += 256) {
        if (uvals[i] >= tau)
            atomicAdd(&slog[(int)load_idx(il, i)], Srow[i]);  // unboosted sim
    }
    __syncthreads();

    float part = 0.f;
    for (int c = tid; c < C_CLASSES; c += 256) {
        float l = slog[c];
        part += (l == 0.0f) ? 0.0f : expf(l);   // logits_mask semantics
    }
    red[tid] = part;
    __syncthreads();
    for (int st = 128; st; st >>= 1) {
        if (tid < st) red[tid] += red[tid + st];
        __syncthreads();
    }
    if (tid == 0) {
        float S = red[0];
        float lt = slog[(int)tgt];
        float et = (lt == 0.0f) ? 0.0f : expf(lt);
        float predict = et / (1e-8f + S);
        g_lossb[b] = -logf(predict + 1e-20f);
    }
}

// ---------------- 6: proxy regularizer: per-row logsumexp over classes ----------------
__global__ void k_reg(const void* __restrict__ il) {
    int warp = threadIdx.x >> 5, lane = threadIdx.x & 31;
    int row = blockIdx.x * 8 + warp;
    const float* r = g_CL + (size_t)row * C_CLASSES;
    float mx = -3.4e38f;
    for (int c = lane; c < C_CLASSES; c += 32) mx = fmaxf(mx, r[c]);
    for (int o = 16; o; o >>= 1) mx = fmaxf(mx, __shfl_xor_sync(0xffffffffu, mx, o));
    float s = 0.f;
    for (int c = lane; c < C_CLASSES; c += 32) s += expf(r[c] - mx);
    for (int o = 16; o; o >>= 1) s += __shfl_xor_sync(0xffffffffu, s, o);
    if (lane == 0) {
        float lse = mx + logf(s);
        g_regb[row] = lse - r[(int)load_idx(il, row)];   // -logp[target]
    }
}

// ---------------- 7: deterministic final reduction ----------------
__global__ void k_final(float* __restrict__ out, int out_size) {
    __shared__ float red[256];
    int tid = threadIdx.x;
    float s = 0.f;
    for (int i = tid; i < BATCH; i += 256) s += g_lossb[i];
    red[tid] = s;
    __syncthreads();
    for (int st = 128; st; st >>= 1) {
        if (tid < st) red[tid] += red[tid + st];
        __syncthreads();
    }
    float lc = red[0] / (float)BATCH;
    __syncthreads();
    s = 0.f;
    for (int i = tid; i < ALLNUM; i += 256) s += g_regb[i];
    red[tid] = s;
    __syncthreads();
    for (int st = 128; st; st >>= 1) {
        if (tid < st) red[tid] += red[tid + st];
        __syncthreads();
    }
    if (tid == 0) {
        float reg = red[0] / (float)ALLNUM;
        out[0] = lc + LAMB * reg;
        if (out_size > 1) out[1] = lc;
    }
}

// ---------------- launch ----------------
extern "C" void kernel_launch(void* const* d_in, const int* in_sizes, int n_in,
                              void* d_out, int out_size) {
    const float* input   = (const float*)d_in[0];
    const void*  target  = d_in[1];
    const float* proxies = (const float*)d_in[2];
    const void*  il      = d_in[3];
    float* out = (float*)d_out;

    k_detect<<<1, 32>>>((const unsigned int*)target);
    k_norm<<<ALLNUM / 256, 256>>>(proxies);
    k_groupsum<<<DIMK, 256>>>(proxies, il);

    dim3 g1(ALLNUM / 128, BATCH / 128);    // (64, 16)
    k_gemm_sim<<<g1, 256>>>(input, proxies);

    dim3 g2(C_CLASSES / 128, ALLNUM / 128); // (8, 64)
    k_gemm_reg<<<g2, 256>>>(proxies);

    k_classify<<<BATCH, 256>>>(target, il);
    k_reg<<<ALLNUM / 8, 256>>>(il);
    k_final<<<1, 256>>>(out, out_size);
}

// round 4
// speedup vs baseline: 1.7035x; 1.7035x over previous
#include <cuda_runtime.h>
#include <cuda_bf16.h>
#include <cstdint>
#include <math.h>

#define C_CLASSES 1024
#define ALLNUM    8192
#define DIMK      512
#define TOPK      410
#define BATCH     2048
#define LAMB      0.3f

// ---------------- scratch (static device globals: no allocation) ----------------
__device__ float g_invnorm[ALLNUM];
__device__ float g_G[DIMK * C_CLASSES];                    // fp32 class-summed centers
__device__ float g_sim[(size_t)BATCH * ALLNUM];            // 64 MB
__device__ float g_CL[(size_t)ALLNUM * C_CLASSES];         // 32 MB
__device__ float g_lossb[BATCH];
__device__ float g_regb[ALLNUM];
__device__ int   g_is64;

// bf16 hi/lo split operands
__device__ __nv_bfloat16 gAh[(size_t)BATCH * DIMK];        // input split      [2048][512]
__device__ __nv_bfloat16 gAl[(size_t)BATCH * DIMK];
__device__ __nv_bfloat16 gBh[(size_t)DIMK * ALLNUM];       // scaled centers   [512][8192]
__device__ __nv_bfloat16 gBl[(size_t)DIMK * ALLNUM];
__device__ __nv_bfloat16 gCTh[(size_t)ALLNUM * DIMK];      // centers^T        [8192][512]
__device__ __nv_bfloat16 gCTl[(size_t)ALLNUM * DIMK];
__device__ __nv_bfloat16 gGh[(size_t)DIMK * C_CLASSES];    // G split          [512][1024]
__device__ __nv_bfloat16 gGl[(size_t)DIMK * C_CLASSES];

// ---------------- helpers ----------------
__device__ __forceinline__ long long load_idx(const void* p, int i) {
    if (g_is64) return ((const long long*)p)[i];
    return (long long)((const int*)p)[i];
}
__device__ __forceinline__ uint32_t sptr(const void* p) {
    return (uint32_t)__cvta_generic_to_shared(p);
}
__device__ __forceinline__ void ldsm_x4(uint32_t r[4], uint32_t addr) {
    asm volatile("ldmatrix.sync.aligned.m8n8.x4.shared.b16 {%0,%1,%2,%3}, [%4];"
                 : "=r"(r[0]), "=r"(r[1]), "=r"(r[2]), "=r"(r[3]) : "r"(addr));
}
__device__ __forceinline__ void ldsm_x4_t(uint32_t r[4], uint32_t addr) {
    asm volatile("ldmatrix.sync.aligned.m8n8.x4.trans.shared.b16 {%0,%1,%2,%3}, [%4];"
                 : "=r"(r[0]), "=r"(r[1]), "=r"(r[2]), "=r"(r[3]) : "r"(addr));
}
__device__ __forceinline__ void mma_bf16(float d[4], const uint32_t a[4],
                                         const uint32_t b[2]) {
    asm volatile(
        "mma.sync.aligned.m16n8k16.row.col.f32.bf16.bf16.f32 "
        "{%0,%1,%2,%3}, {%4,%5,%6,%7}, {%8,%9}, {%0,%1,%2,%3};"
        : "+f"(d[0]), "+f"(d[1]), "+f"(d[2]), "+f"(d[3])
        : "r"(a[0]), "r"(a[1]), "r"(a[2]), "r"(a[3]), "r"(b[0]), "r"(b[1]));
}

// ---------------- 0: int64 vs int32 index dtype detection ----------------
__global__ void k_detect(const unsigned int* __restrict__ t) {
    if (threadIdx.x == 0) {
        int is64 = 1;
        for (int k = 0; k < 8; k++)
            if (t[2 * k + 1] != 0u) is64 = 0;
        g_is64 = is64;
    }
}

// ---------------- 1: column inverse norms ----------------
__global__ void k_norm(const float* __restrict__ P) {
    int a = blockIdx.x * blockDim.x + threadIdx.x;
    float s = 0.f;
    for (int d = 0; d < DIMK; d++) {
        float v = P[(size_t)d * ALLNUM + a];
        s = fmaf(v, v, s);
    }
    g_invnorm[a] = 1.0f / fmaxf(sqrtf(s), 1e-12f);
}

// ---------------- 2: class-summed centers G[d][c] (fp32) ----------------
__global__ void k_groupsum(const float* __restrict__ P, const void* __restrict__ il) {
    __shared__ float g[C_CLASSES];
    int d = blockIdx.x;
    for (int c = threadIdx.x; c < C_CLASSES; c += blockDim.x) g[c] = 0.f;
    __syncthreads();
    const float* Pd = P + (size_t)d * ALLNUM;
    for (int a = threadIdx.x; a < ALLNUM; a += blockDim.x)
        atomicAdd(&g[(int)load_idx(il, a)], Pd[a] * g_invnorm[a]);
    __syncthreads();
    for (int c = threadIdx.x; c < C_CLASSES; c += blockDim.x)
        g_G[d * C_CLASSES + c] = g[c];
}

// ---------------- 3a: split input A -> bf16 hi/lo ----------------
__global__ void k_split_A(const float* __restrict__ A) {
    int i = blockIdx.x * 256 + threadIdx.x;
    float x = A[i];
    __nv_bfloat16 h = __float2bfloat16(x);
    gAh[i] = h;
    gAl[i] = __float2bfloat16(x - __bfloat162float(h));
}

// ---------------- 3b: split scaled centers -> K-major bf16 + transposed bf16 ----------------
__global__ __launch_bounds__(256) void k_split_PT(const float* __restrict__ P) {
    __shared__ __nv_bfloat16 sh[64 * 66], sl[64 * 66];
    int ab = blockIdx.x * 64, kb = blockIdx.y * 64;
    int tid = threadIdx.x;
#pragma unroll
    for (int r = 0; r < 16; r++) {
        int idx = tid + r * 256;
        int kr = idx >> 6, ac = idx & 63;
        size_t go = (size_t)(kb + kr) * ALLNUM + ab + ac;
        float v = P[go] * g_invnorm[ab + ac];
        __nv_bfloat16 h = __float2bfloat16(v);
        __nv_bfloat16 l = __float2bfloat16(v - __bfloat162float(h));
        gBh[go] = h; gBl[go] = l;
        sh[kr * 66 + ac] = h; sl[kr * 66 + ac] = l;
    }
    __syncthreads();
#pragma unroll
    for (int r = 0; r < 16; r++) {
        int idx = tid + r * 256;
        int ar = idx >> 6, kc = idx & 63;
        size_t go = (size_t)(ab + ar) * DIMK + kb + kc;
        gCTh[go] = sh[kc * 66 + ar];
        gCTl[go] = sl[kc * 66 + ar];
    }
}

// ---------------- 3c: split G -> bf16 hi/lo ----------------
__global__ void k_split_G() {
    int i = blockIdx.x * 256 + threadIdx.x;
    float x = g_G[i];
    __nv_bfloat16 h = __float2bfloat16(x);
    gGh[i] = h;
    gGl[i] = __float2bfloat16(x - __bfloat162float(h));
}

// ---------------- 4: bf16-split tensor-core GEMM (K=512 fixed, lda=512, ldb=ldout=N)
// CTA 128x128, 8 warps (2x4), warp tile 64x32, kstep 32.
// acc += Ah*Bh + Ah*Bl + Al*Bh  (fp32 accumulate)
__global__ __launch_bounds__(256, 2) void k_mma(const __nv_bfloat16* __restrict__ Ah,
                                                const __nv_bfloat16* __restrict__ Al,
                                                const __nv_bfloat16* __restrict__ Bh,
                                                const __nv_bfloat16* __restrict__ Bl,
                                                float* __restrict__ Out, int N) {
    __shared__ __align__(16) __nv_bfloat16 sAh[128 * 40], sAl[128 * 40];
    __shared__ __align__(16) __nv_bfloat16 sBh[32 * 136], sBl[32 * 136];

    int tid = threadIdx.x;
    int lane = tid & 31, w = tid >> 5;
    int wm = (w & 1) * 64, wn = (w >> 1) * 32;
    int bm = blockIdx.y * 128, bn = blockIdx.x * 128;

    float acc[4][4][4];
#pragma unroll
    for (int i = 0; i < 4; i++)
#pragma unroll
        for (int j = 0; j < 4; j++)
#pragma unroll
            for (int q = 0; q < 4; q++) acc[i][j][q] = 0.f;

    for (int k0 = 0; k0 < DIMK; k0 += 32) {
#pragma unroll
        for (int r = 0; r < 2; r++) {
            int idx = tid + r * 256;
            int row = idx >> 2, c4 = (idx & 3) * 8;
            size_t ga = (size_t)(bm + row) * DIMK + k0 + c4;
            *(uint4*)&sAh[row * 40 + c4] = *(const uint4*)&Ah[ga];
            *(uint4*)&sAl[row * 40 + c4] = *(const uint4*)&Al[ga];
            int brow = idx >> 4, bc = (idx & 15) * 8;
            size_t gb = (size_t)(k0 + brow) * N + bn + bc;
            *(uint4*)&sBh[brow * 136 + bc] = *(const uint4*)&Bh[gb];
            *(uint4*)&sBl[brow * 136 + bc] = *(const uint4*)&Bl[gb];
        }
        __syncthreads();
#pragma unroll
        for (int kf = 0; kf < 32; kf += 16) {
            uint32_t ah[4][4], al[4][4], bh[4][2], bl[4][2], t[4];
            int aoff = (wm + (lane & 15)) * 40 + kf + (lane >> 4) * 8;
#pragma unroll
            for (int mt = 0; mt < 4; mt++) {
                ldsm_x4(ah[mt], sptr(sAh + aoff + mt * 16 * 40));
                ldsm_x4(al[mt], sptr(sAl + aoff + mt * 16 * 40));
            }
            int boff = (kf + (lane & 15)) * 136 + wn + (lane >> 4) * 8;
            ldsm_x4_t(t, sptr(sBh + boff));
            bh[0][0] = t[0]; bh[0][1] = t[1]; bh[1][0] = t[2]; bh[1][1] = t[3];
            ldsm_x4_t(t, sptr(sBh + boff + 16));
            bh[2][0] = t[0]; bh[2][1] = t[1]; bh[3][0] = t[2]; bh[3][1] = t[3];
            ldsm_x4_t(t, sptr(sBl + boff));
            bl[0][0] = t[0]; bl[0][1] = t[1]; bl[1][0] = t[2]; bl[1][1] = t[3];
            ldsm_x4_t(t, sptr(sBl + boff + 16));
            bl[2][0] = t[0]; bl[2][1] = t[1]; bl[3][0] = t[2]; bl[3][1] = t[3];
#pragma unroll
            for (int mt = 0; mt < 4; mt++)
#pragma unroll
                for (int nt = 0; nt < 4; nt++) {
                    mma_bf16(acc[mt][nt], ah[mt], bh[nt]);
                    mma_bf16(acc[mt][nt], ah[mt], bl[nt]);
                    mma_bf16(acc[mt][nt], al[mt], bh[nt]);
                }
        }
        __syncthreads();
    }
    int g = lane >> 2, t4 = (lane & 3) * 2;
#pragma unroll
    for (int mt = 0; mt < 4; mt++)
#pragma unroll
        for (int nt = 0; nt < 4; nt++) {
            int r0 = bm + wm + mt * 16 + g;
            int c = bn + wn + nt * 8 + t4;
            *(float2*)&Out[(size_t)r0 * N + c] =
                make_float2(acc[mt][nt][0], acc[mt][nt][1]);
            *(float2*)&Out[(size_t)(r0 + 8) * N + c] =
                make_float2(acc[mt][nt][2], acc[mt][nt][3]);
        }
}

// ---------------- 5: per-row top-k threshold + masked-softmax classify loss ----------------
__global__ __launch_bounds__(256) void k_classify(const void* __restrict__ target,
                                                  const void* __restrict__ il) {
    __shared__ unsigned int uvals[ALLNUM];   // 32 KB
    __shared__ unsigned int hist[256];
    __shared__ float slog[C_CLASSES];        // 4 KB
    __shared__ float red[256];
    __shared__ unsigned int sh_prefix;
    __shared__ int sh_k;

    int tid = threadIdx.x;
    int lane = tid & 31;
    int b = blockIdx.x;
    long long tgt = load_idx(target, b);
    const float* Srow = g_sim + (size_t)b * ALLNUM;

    for (int i = tid; i < ALLNUM; i += 256) {
        float v = Srow[i] + ((load_idx(il, i) == tgt) ? 1000.0f : 0.0f);
        unsigned int bits = __float_as_uint(v);
        uvals[i] = (bits & 0x80000000u) ? ~bits : (bits | 0x80000000u);
    }
    for (int c = tid; c < C_CLASSES; c += 256) slog[c] = 0.f;
    if (tid == 0) { sh_prefix = 0u; sh_k = TOPK; }
    __syncthreads();

    for (int shift = 24; shift >= 0; shift -= 8) {
        hist[tid] = 0u;
        __syncthreads();
        unsigned int pfx = sh_prefix;
        int k = sh_k;
        unsigned int hm = (shift == 24) ? 0u : (0xFFFFFFFFu << (shift + 8));
        // warp-aggregated histogram: values cluster heavily in a few bins,
        // plain atomics serialize at ~32cyc/warp on same-address.
        for (int i = tid; i < ALLNUM; i += 256) {   // 32 uniform trips
            unsigned int u = uvals[i];
            int bin = ((u & hm) == pfx) ? (int)((u >> shift) & 255u) : -1;
            unsigned int m = __match_any_sync(0xffffffffu, bin);
            if (bin >= 0 && lane == (int)(__ffs(m) - 1))
                atomicAdd(&hist[bin], (unsigned int)__popc(m));
        }
        __syncthreads();
        if (tid == 0) {
            int cum = 0, d = 255;
            for (; d >= 0; d--) { cum += (int)hist[d]; if (cum >= k) break; }
            sh_k = k - (cum - (int)hist[d]);
            sh_prefix = pfx | ((unsigned int)d << shift);
        }
        __syncthreads();
    }
    unsigned int tau = sh_prefix;

    for (int i = tid; i < ALLNUM; i += 256) {
        if (uvals[i] >= tau)
            atomicAdd(&slog[(int)load_idx(il, i)], Srow[i]);
    }
    __syncthreads();

    float part = 0.f;
    for (int c = tid; c < C_CLASSES; c += 256) {
        float l = slog[c];
        part += (l == 0.0f) ? 0.0f : expf(l);
    }
    red[tid] = part;
    __syncthreads();
    for (int st = 128; st; st >>= 1) {
        if (tid < st) red[tid] += red[tid + st];
        __syncthreads();
    }
    if (tid == 0) {
        float S = red[0];
        float lt = slog[(int)tgt];
        float et = (lt == 0.0f) ? 0.0f : expf(lt);
        float predict = et / (1e-8f + S);
        g_lossb[b] = -logf(predict + 1e-20f);
    }
}

// ---------------- 6: proxy regularizer: per-row logsumexp over classes ----------------
__global__ void k_reg(const void* __restrict__ il) {
    int warp = threadIdx.x >> 5, lane = threadIdx.x & 31;
    int row = blockIdx.x * 8 + warp;
    const float* r = g_CL + (size_t)row * C_CLASSES;
    float mx = -3.4e38f;
    for (int c = lane; c < C_CLASSES; c += 32) mx = fmaxf(mx, r[c]);
    for (int o = 16; o; o >>= 1) mx = fmaxf(mx, __shfl_xor_sync(0xffffffffu, mx, o));
    float s = 0.f;
    for (int c = lane; c < C_CLASSES; c += 32) s += expf(r[c] - mx);
    for (int o = 16; o; o >>= 1) s += __shfl_xor_sync(0xffffffffu, s, o);
    if (lane == 0) {
        float lse = mx + logf(s);
        g_regb[row] = lse - r[(int)load_idx(il, row)];
    }
}

// ---------------- 7: deterministic final reduction ----------------
__global__ void k_final(float* __restrict__ out, int out_size) {
    __shared__ float red[256];
    int tid = threadIdx.x;
    float s = 0.f;
    for (int i = tid; i < BATCH; i += 256) s += g_lossb[i];
    red[tid] = s;
    __syncthreads();
    for (int st = 128; st; st >>= 1) {
        if (tid < st) red[tid] += red[tid + st];
        __syncthreads();
    }
    float lc = red[0] / (float)BATCH;
    __syncthreads();
    s = 0.f;
    for (int i = tid; i < ALLNUM; i += 256) s += g_regb[i];
    red[tid] = s;
    __syncthreads();
    for (int st = 128; st; st >>= 1) {
        if (tid < st) red[tid] += red[tid + st];
        __syncthreads();
    }
    if (tid == 0) {
        float reg = red[0] / (float)ALLNUM;
        out[0] = lc + LAMB * reg;
        if (out_size > 1) out[1] = lc;
    }
}

// ---------------- launch ----------------
extern "C" void kernel_launch(void* const* d_in, const int* in_sizes, int n_in,
                              void* d_out, int out_size) {
    const float* input   = (const float*)d_in[0];
    const void*  target  = d_in[1];
    const float* proxies = (const float*)d_in[2];
    const void*  il      = d_in[3];
    float* out = (float*)d_out;

    static __nv_bfloat16 *pAh, *pAl, *pBh, *pBl, *pCTh, *pCTl, *pGh, *pGl;
    static float *pSim, *pCL;
    static bool init = false;
    if (!init) {
        cudaGetSymbolAddress((void**)&pAh, gAh);
        cudaGetSymbolAddress((void**)&pAl, gAl);
        cudaGetSymbolAddress((void**)&pBh, gBh);
        cudaGetSymbolAddress((void**)&pBl, gBl);
        cudaGetSymbolAddress((void**)&pCTh, gCTh);
        cudaGetSymbolAddress((void**)&pCTl, gCTl);
        cudaGetSymbolAddress((void**)&pGh, gGh);
        cudaGetSymbolAddress((void**)&pGl, gGl);
        cudaGetSymbolAddress((void**)&pSim, g_sim);
        cudaGetSymbolAddress((void**)&pCL, g_CL);
        init = true;
    }

    k_detect<<<1, 32>>>((const unsigned int*)target);
    k_norm<<<ALLNUM / 256, 256>>>(proxies);
    k_groupsum<<<DIMK, 256>>>(proxies, il);

    k_split_A<<<(BATCH * DIMK) / 256, 256>>>(input);
    dim3 gpt(ALLNUM / 64, DIMK / 64);
    k_split_PT<<<gpt, 256>>>(proxies);
    k_split_G<<<(DIMK * C_CLASSES) / 256, 256>>>();

    dim3 g1(ALLNUM / 128, BATCH / 128);     // (64, 16)
    k_mma<<<g1, 256>>>(pAh, pAl, pBh, pBl, pSim, ALLNUM);

    dim3 g2(C_CLASSES / 128, ALLNUM / 128); // (8, 64)
    k_mma<<<g2, 256>>>(pCTh, pCTl, pGh, pGl, pCL, C_CLASSES);

    k_classify<<<BATCH, 256>>>(target, il);
    k_reg<<<ALLNUM / 8, 256>>>(il);
    k_final<<<1, 256>>>(out, out_size);
}

// round 9
// speedup vs baseline: 1.8824x; 1.1051x over previous
#include <cuda_runtime.h>
#include <cuda_bf16.h>
#include <cstdint>
#include <math.h>

#define C_CLASSES 1024
#define ALLNUM    8192
#define DIMK      512
#define TOPK      410
#define BATCH     2048
#define LAMB      0.3f

// ---------------- scratch (static device globals: no allocation) ----------------
__device__ float g_invnorm[ALLNUM];
__device__ float g_sim[(size_t)BATCH * ALLNUM];            // 64 MB
__device__ float g_CL[(size_t)ALLNUM * C_CLASSES];         // 32 MB
__device__ float g_lossb[BATCH];
__device__ float g_regb[ALLNUM];
__device__ int   g_is64;

// bf16 hi/lo split operands
__device__ __nv_bfloat16 gAh[(size_t)BATCH * DIMK];        // input [2048][512]
__device__ __nv_bfloat16 gAl[(size_t)BATCH * DIMK];
__device__ __nv_bfloat16 gBh[(size_t)DIMK * ALLNUM];       // scaled centers [512][8192] K-major
__device__ __nv_bfloat16 gBl[(size_t)DIMK * ALLNUM];
__device__ __nv_bfloat16 gCTh[(size_t)ALLNUM * DIMK];      // centers^T [8192][512]
__device__ __nv_bfloat16 gCTl[(size_t)ALLNUM * DIMK];
__device__ __nv_bfloat16 gGh[(size_t)DIMK * C_CLASSES];    // G [512][1024] K-major
__device__ __nv_bfloat16 gGl[(size_t)DIMK * C_CLASSES];

// ---------------- helpers ----------------
__device__ __forceinline__ long long load_idx(const void* p, int i) {
    if (g_is64) return ((const long long*)p)[i];
    return (long long)((const int*)p)[i];
}
__device__ __forceinline__ uint32_t sptr(const void* p) {
    return (uint32_t)__cvta_generic_to_shared(p);
}
__device__ __forceinline__ void cpa16(uint32_t saddr, const void* g) {
    asm volatile("cp.async.cg.shared.global [%0], [%1], 16;" :: "r"(saddr), "l"(g));
}
#define CPA_COMMIT() asm volatile("cp.async.commit_group;" ::: "memory")
#define CPA_WAIT(n)  asm volatile("cp.async.wait_group %0;" :: "n"(n) : "memory")

__device__ __forceinline__ void ldsm_x4(uint32_t r[4], uint32_t addr) {
    asm volatile("ldmatrix.sync.aligned.m8n8.x4.shared.b16 {%0,%1,%2,%3}, [%4];"
                 : "=r"(r[0]), "=r"(r[1]), "=r"(r[2]), "=r"(r[3]) : "r"(addr));
}
__device__ __forceinline__ void ldsm_x4_t(uint32_t r[4], uint32_t addr) {
    asm volatile("ldmatrix.sync.aligned.m8n8.x4.trans.shared.b16 {%0,%1,%2,%3}, [%4];"
                 : "=r"(r[0]), "=r"(r[1]), "=r"(r[2]), "=r"(r[3]) : "r"(addr));
}
__device__ __forceinline__ void mma_bf16(float d[4], const uint32_t a[4],
                                         const uint32_t b[2]) {
    asm volatile(
        "mma.sync.aligned.m16n8k16.row.col.f32.bf16.bf16.f32 "
        "{%0,%1,%2,%3}, {%4,%5,%6,%7}, {%8,%9}, {%0,%1,%2,%3};"
        : "+f"(d[0]), "+f"(d[1]), "+f"(d[2]), "+f"(d[3])
        : "r"(a[0]), "r"(a[1]), "r"(a[2]), "r"(a[3]), "r"(b[0]), "r"(b[1]));
}

// ---------------- 0: int64 vs int32 index dtype detection ----------------
__global__ void k_detect(const unsigned int* __restrict__ t) {
    if (threadIdx.x == 0) {
        int is64 = 1;
        for (int k = 0; k < 8; k++)
            if (t[2 * k + 1] != 0u) is64 = 0;
        g_is64 = is64;
    }
}

// ---------------- 1: column inverse norms ----------------
__global__ void k_norm(const float* __restrict__ P) {
    int a = blockIdx.x * blockDim.x + threadIdx.x;
    float s = 0.f;
    for (int d = 0; d < DIMK; d++) {
        float v = P[(size_t)d * ALLNUM + a];
        s = fmaf(v, v, s);
    }
    g_invnorm[a] = 1.0f / fmaxf(sqrtf(s), 1e-12f);
}

// ---------------- 2: class-summed centers -> bf16 split G[d][c], K-major ----------------
__global__ void k_groupsum(const float* __restrict__ P, const void* __restrict__ il) {
    __shared__ float g[C_CLASSES];
    int d = blockIdx.x;                               // 512 blocks
    for (int c = threadIdx.x; c < C_CLASSES; c += blockDim.x) g[c] = 0.f;
    __syncthreads();
    const float* Pd = P + (size_t)d * ALLNUM;
    for (int a = threadIdx.x; a < ALLNUM; a += blockDim.x)
        atomicAdd(&g[(int)load_idx(il, a)], Pd[a] * g_invnorm[a]);
    __syncthreads();
    for (int c = threadIdx.x; c < C_CLASSES; c += blockDim.x) {
        float x = g[c];
        __nv_bfloat16 h = __float2bfloat16(x);
        gGh[d * C_CLASSES + c] = h;
        gGl[d * C_CLASSES + c] = __float2bfloat16(x - __bfloat162float(h));
    }
}

// ---------------- 3a: split input A -> bf16 hi/lo ----------------
__global__ void k_split_A(const float* __restrict__ A) {
    int i = blockIdx.x * 256 + threadIdx.x;
    float x = A[i];
    __nv_bfloat16 h = __float2bfloat16(x);
    gAh[i] = h;
    gAl[i] = __float2bfloat16(x - __bfloat162float(h));
}

// ---------------- 3b: split scaled centers -> K-major bf16 + transposed bf16 ----------------
__global__ __launch_bounds__(256) void k_split_PT(const float* __restrict__ P) {
    __shared__ __nv_bfloat16 sh[64 * 66], sl[64 * 66];
    int ab = blockIdx.x * 64, kb = blockIdx.y * 64;
    int tid = threadIdx.x;
#pragma unroll
    for (int r = 0; r < 16; r++) {
        int idx = tid + r * 256;
        int kr = idx >> 6, ac = idx & 63;
        size_t go = (size_t)(kb + kr) * ALLNUM + ab + ac;
        float v = P[go] * g_invnorm[ab + ac];
        __nv_bfloat16 h = __float2bfloat16(v);
        __nv_bfloat16 l = __float2bfloat16(v - __bfloat162float(h));
        gBh[go] = h; gBl[go] = l;
        sh[kr * 66 + ac] = h; sl[kr * 66 + ac] = l;
    }
    __syncthreads();
#pragma unroll
    for (int r = 0; r < 16; r++) {
        int idx = tid + r * 256;
        int ar = idx >> 6, kc = idx & 63;
        size_t go = (size_t)(ab + ar) * DIMK + kb + kc;
        gCTh[go] = sh[kc * 66 + ar];
        gCTl[go] = sl[kc * 66 + ar];
    }
}

// ---------------- 4: bf16-split tensor-core GEMM, cp.async double-buffered ----------------
// C[M][N] = A[M][512] . B[512][N], 3 passes (AhBh + AhBl + AlBh), fp32 accumulate.
// CTA 128x128, 8 warps (2x4), warp tile 64x32, K chunk 32, 2-stage pipeline.
// dynamic smem layout (bf16 elements):
//   Ah: [2][128*40] @ 0      Al: @ 10240
//   Bh: [2][32*136] @ 20480  Bl: @ 29184      total 37888 elems = 75776 B
#define MMA_SMEM 75776
__global__ __launch_bounds__(256, 2) void k_mma(const __nv_bfloat16* __restrict__ Ah,
                                                const __nv_bfloat16* __restrict__ Al,
                                                const __nv_bfloat16* __restrict__ Bh,
                                                const __nv_bfloat16* __restrict__ Bl,
                                                float* __restrict__ Out, int N) {
    extern __shared__ __align__(16) __nv_bfloat16 smem[];
    __nv_bfloat16* bAh = smem;
    __nv_bfloat16* bAl = smem + 10240;
    __nv_bfloat16* bBh = smem + 20480;
    __nv_bfloat16* bBl = smem + 29184;

    int tid = threadIdx.x;
    int lane = tid & 31, w = tid >> 5;
    int wm = (w & 1) * 64, wn = (w >> 1) * 32;
    int bm = blockIdx.y * 128, bn = blockIdx.x * 128;

    float acc[4][4][4];
#pragma unroll
    for (int i = 0; i < 4; i++)
#pragma unroll
        for (int j = 0; j < 4; j++)
#pragma unroll
            for (int q = 0; q < 4; q++) acc[i][j][q] = 0.f;

#define LOAD_STAGE(k0, s)                                                        \
    do {                                                                         \
        __nv_bfloat16* dAh = bAh + (s) * 5120;                                   \
        __nv_bfloat16* dAl = bAl + (s) * 5120;                                   \
        __nv_bfloat16* dBh = bBh + (s) * 4352;                                   \
        __nv_bfloat16* dBl = bBl + (s) * 4352;                                   \
        _Pragma("unroll")                                                        \
        for (int r = 0; r < 2; r++) {                                            \
            int idx = tid + r * 256;                                             \
            int row = idx >> 2, c4 = (idx & 3) * 8;                              \
            size_t ga = (size_t)(bm + row) * DIMK + (k0) + c4;                   \
            cpa16(sptr(dAh + row * 40 + c4), Ah + ga);                           \
            cpa16(sptr(dAl + row * 40 + c4), Al + ga);                           \
            int br = idx >> 4, bc = (idx & 15) * 8;                              \
            size_t gb = (size_t)((k0) + br) * N + bn + bc;                       \
            cpa16(sptr(dBh + br * 136 + bc), Bh + gb);                           \
            cpa16(sptr(dBl + br * 136 + bc), Bl + gb);                           \
        }                                                                        \
    } while (0)

    LOAD_STAGE(0, 0);
    CPA_COMMIT();

    for (int c = 0; c < 16; c++) {
        int s = c & 1;
        if (c + 1 < 16) {
            LOAD_STAGE((c + 1) * 32, s ^ 1);
            CPA_COMMIT();
            CPA_WAIT(1);             // stage c resident; c+1 may be in flight
        } else {
            CPA_WAIT(0);
        }
        __syncthreads();

        const __nv_bfloat16* sAh = bAh + s * 5120;
        const __nv_bfloat16* sAl = bAl + s * 5120;
        const __nv_bfloat16* sBh = bBh + s * 4352;
        const __nv_bfloat16* sBl = bBl + s * 4352;
#pragma unroll
        for (int kf = 0; kf < 32; kf += 16) {
            uint32_t ah[4][4], al[4][4], bh[4][2], bl[4][2], t[4];
            int aoff = (wm + (lane & 15)) * 40 + kf + (lane >> 4) * 8;
#pragma unroll
            for (int mt = 0; mt < 4; mt++) {
                ldsm_x4(ah[mt], sptr(sAh + aoff + mt * 16 * 40));
                ldsm_x4(al[mt], sptr(sAl + aoff + mt * 16 * 40));
            }
            int boff = (kf + (lane & 15)) * 136 + wn + (lane >> 4) * 8;
            ldsm_x4_t(t, sptr(sBh + boff));
            bh[0][0] = t[0]; bh[0][1] = t[1]; bh[1][0] = t[2]; bh[1][1] = t[3];
            ldsm_x4_t(t, sptr(sBh + boff + 16));
            bh[2][0] = t[0]; bh[2][1] = t[1]; bh[3][0] = t[2]; bh[3][1] = t[3];
            ldsm_x4_t(t, sptr(sBl + boff));
            bl[0][0] = t[0]; bl[0][1] = t[1]; bl[1][0] = t[2]; bl[1][1] = t[3];
            ldsm_x4_t(t, sptr(sBl + boff + 16));
            bl[2][0] = t[0]; bl[2][1] = t[1]; bl[3][0] = t[2]; bl[3][1] = t[3];
#pragma unroll
            for (int mt = 0; mt < 4; mt++)
#pragma unroll
                for (int nt = 0; nt < 4; nt++) {
                    mma_bf16(acc[mt][nt], ah[mt], bh[nt]);
                    mma_bf16(acc[mt][nt], ah[mt], bl[nt]);
                    mma_bf16(acc[mt][nt], al[mt], bh[nt]);
                }
        }
        __syncthreads();   // compute of stage s done before it is reloaded at c+2
    }

    int g = lane >> 2, t4 = (lane & 3) * 2;
#pragma unroll
    for (int mt = 0; mt < 4; mt++)
#pragma unroll
        for (int nt = 0; nt < 4; nt++) {
            int r0 = bm + wm + mt * 16 + g;
            int cc = bn + wn + nt * 8 + t4;
            *(float2*)&Out[(size_t)r0 * N + cc] =
                make_float2(acc[mt][nt][0], acc[mt][nt][1]);
            *(float2*)&Out[(size_t)(r0 + 8) * N + cc] =
                make_float2(acc[mt][nt][2], acc[mt][nt][3]);
        }
#undef LOAD_STAGE
}

// ---------------- 5: per-row top-k threshold + masked-softmax classify loss ----------------
__global__ __launch_bounds__(256) void k_classify(const void* __restrict__ target,
                                                  const void* __restrict__ il) {
    __shared__ unsigned int uvals[ALLNUM];   // 32 KB
    __shared__ unsigned int hist[256];
    __shared__ float slog[C_CLASSES];        // 4 KB
    __shared__ float red[256];
    __shared__ unsigned int sh_prefix;
    __shared__ int sh_k;

    int tid = threadIdx.x;
    int lane = tid & 31;
    int b = blockIdx.x;
    long long tgt = load_idx(target, b);
    const float* Srow = g_sim + (size_t)b * ALLNUM;

    for (int i = tid; i < ALLNUM; i += 256) {
        float v = Srow[i] + ((load_idx(il, i) == tgt) ? 1000.0f : 0.0f);
        unsigned int bits = __float_as_uint(v);
        uvals[i] = (bits & 0x80000000u) ? ~bits : (bits | 0x80000000u);
    }
    for (int c = tid; c < C_CLASSES; c += 256) slog[c] = 0.f;
    if (tid == 0) { sh_prefix = 0u; sh_k = TOPK; }
    __syncthreads();

    for (int shift = 24; shift >= 0; shift -= 8) {
        hist[tid] = 0u;
        __syncthreads();
        unsigned int pfx = sh_prefix;
        int k = sh_k;
        unsigned int hm = (shift == 24) ? 0u : (0xFFFFFFFFu << (shift + 8));
        for (int i = tid; i < ALLNUM; i += 256) {
            unsigned int u = uvals[i];
            int bin = ((u & hm) == pfx) ? (int)((u >> shift) & 255u) : -1;
            unsigned int m = __match_any_sync(0xffffffffu, bin);
            if (bin >= 0 && lane == (int)(__ffs(m) - 1))
                atomicAdd(&hist[bin], (unsigned int)__popc(m));
        }
        __syncthreads();
        if (tid == 0) {
            int cum = 0, d = 255;
            for (; d >= 0; d--) { cum += (int)hist[d]; if (cum >= k) break; }
            sh_k = k - (cum - (int)hist[d]);
            sh_prefix = pfx | ((unsigned int)d << shift);
        }
        __syncthreads();
    }
    unsigned int tau = sh_prefix;

    for (int i = tid; i < ALLNUM; i += 256) {
        if (uvals[i] >= tau)
            atomicAdd(&slog[(int)load_idx(il, i)], Srow[i]);
    }
    __syncthreads();

    float part = 0.f;
    for (int c = tid; c < C_CLASSES; c += 256) {
        float l = slog[c];
        part += (l == 0.0f) ? 0.0f : expf(l);
    }
    red[tid] = part;
    __syncthreads();
    for (int st = 128; st; st >>= 1) {
        if (tid < st) red[tid] += red[tid + st];
        __syncthreads();
    }
    if (tid == 0) {
        float S = red[0];
        float lt = slog[(int)tgt];
        float et = (lt == 0.0f) ? 0.0f : expf(lt);
        float predict = et / (1e-8f + S);
        g_lossb[b] = -logf(predict + 1e-20f);
    }
}

// ---------------- 6: proxy regularizer: per-row logsumexp over classes ----------------
__global__ void k_reg(const void* __restrict__ il) {
    int warp = threadIdx.x >> 5, lane = threadIdx.x & 31;
    int row = blockIdx.x * 8 + warp;
    const float* r = g_CL + (size_t)row * C_CLASSES;
    float mx = -3.4e38f;
    for (int c = lane; c < C_CLASSES; c += 32) mx = fmaxf(mx, r[c]);
    for (int o = 16; o; o >>= 1) mx = fmaxf(mx, __shfl_xor_sync(0xffffffffu, mx, o));
    float s = 0.f;
    for (int c = lane; c < C_CLASSES; c += 32) s += expf(r[c] - mx);
    for (int o = 16; o; o >>= 1) s += __shfl_xor_sync(0xffffffffu, s, o);
    if (lane == 0) {
        float lse = mx + logf(s);
        g_regb[row] = lse - r[(int)load_idx(il, row)];
    }
}

// ---------------- 7: deterministic final reduction ----------------
__global__ void k_final(float* __restrict__ out, int out_size) {
    __shared__ float red[256];
    int tid = threadIdx.x;
    float s = 0.f;
    for (int i = tid; i < BATCH; i += 256) s += g_lossb[i];
    red[tid] = s;
    __syncthreads();
    for (int st = 128; st; st >>= 1) {
        if (tid < st) red[tid] += red[tid + st];
        __syncthreads();
    }
    float lc = red[0] / (float)BATCH;
    __syncthreads();
    s = 0.f;
    for (int i = tid; i < ALLNUM; i += 256) s += g_regb[i];
    red[tid] = s;
    __syncthreads();
    for (int st = 128; st; st >>= 1) {
        if (tid < st) red[tid] += red[tid + st];
        __syncthreads();
    }
    if (tid == 0) {
        float reg = red[0] / (float)ALLNUM;
        out[0] = lc + LAMB * reg;
        if (out_size > 1) out[1] = lc;
    }
}

// ---------------- launch ----------------
extern "C" void kernel_launch(void* const* d_in, const int* in_sizes, int n_in,
                              void* d_out, int out_size) {
    const float* input   = (const float*)d_in[0];
    const void*  target  = d_in[1];
    const float* proxies = (const float*)d_in[2];
    const void*  il      = d_in[3];
    float* out = (float*)d_out;

    static __nv_bfloat16 *pAh, *pAl, *pBh, *pBl, *pCTh, *pCTl, *pGh, *pGl;
    static float *pSim, *pCL;
    static bool init = false;
    if (!init) {
        cudaGetSymbolAddress((void**)&pAh, gAh);
        cudaGetSymbolAddress((void**)&pAl, gAl);
        cudaGetSymbolAddress((void**)&pBh, gBh);
        cudaGetSymbolAddress((void**)&pBl, gBl);
        cudaGetSymbolAddress((void**)&pCTh, gCTh);
        cudaGetSymbolAddress((void**)&pCTl, gCTl);
        cudaGetSymbolAddress((void**)&pGh, gGh);
        cudaGetSymbolAddress((void**)&pGl, gGl);
        cudaGetSymbolAddress((void**)&pSim, g_sim);
        cudaGetSymbolAddress((void**)&pCL, g_CL);
        cudaFuncSetAttribute(k_mma, cudaFuncAttributeMaxDynamicSharedMemorySize,
                             MMA_SMEM);
        init = true;
    }

    k_detect<<<1, 32>>>((const unsigned int*)target);
    k_norm<<<ALLNUM / 256, 256>>>(proxies);
    k_groupsum<<<DIMK, 256>>>(proxies, il);
    k_split_A<<<(BATCH * DIMK) / 256, 256>>>(input);
    dim3 gpt(ALLNUM / 64, DIMK / 64);
    k_split_PT<<<gpt, 256>>>(proxies);

    // GEMM1: sim = input . centers  (launch #6: ncu -s 5 -c 1 lands here)
    dim3 g1(ALLNUM / 128, BATCH / 128);     // (64, 16)
    k_mma<<<g1, 256, MMA_SMEM>>>(pAh, pAl, pBh, pBl, pSim, ALLNUM);

    // GEMM2: CL = centers^T . G
    dim3 g2(C_CLASSES / 128, ALLNUM / 128); // (8, 64)
    k_mma<<<g2, 256, MMA_SMEM>>>(pCTh, pCTl, pGh, pGl, pCL, C_CLASSES);

    k_classify<<<BATCH, 256>>>(target, il);
    k_reg<<<ALLNUM / 8, 256>>>(il);
    k_final<<<1, 256>>>(out, out_size);
}